// round 1
// baseline (speedup 1.0000x reference)
#include <cuda_runtime.h>
#include <cstdint>

#define Lc   8
#define Hc   4
#define Qc   64
#define Dc   512
#define Nc   2048
#define DFFc 2048

// ---------------- device scratch (no allocations allowed) ----------------
__device__ float g_X[Dc * Nc];                         // current activations [D,N]
__device__ float g_attn[Dc * Nc];                      // attn = X + scatter  [D,N]
__device__ float g_KX[Hc * Qc * Nc];                   // [H,Q,N]
__device__ float g_scores[(size_t)Hc * Nc * Nc];       // [H,N,N]  (64 MB)
__device__ float g_Y[Hc * Dc * Nc];                    // V_h @ X  [H,D,N]
__device__ float g_ff1[DFFc * Nc];                     // [DFF,N]

// ---------------- generic NN SGEMM: C = A@B (+bias)(+relu)(+residual) ----
// A: [M,K] row-major, B: [K,N] row-major, C: [M,N] row-major. All tiles
// 128x128x8, 256 threads, 8x8 microtile per thread. M%128==0, N%128==0, K%8==0.
// mode 0: C = AB
// mode 1: C = relu(AB + bias[row])
// mode 2: C = AB + bias[row] + R[row,col]
__global__ void __launch_bounds__(256) sgemm_nn(
    const float* __restrict__ A, const float* __restrict__ B,
    float* __restrict__ C, int M, int N, int K,
    long long strideA, long long strideC,
    const float* __restrict__ bias, const float* __restrict__ R, int mode)
{
    const int bz = blockIdx.z;
    A += (size_t)bz * strideA;
    C += (size_t)bz * strideC;

    __shared__ float As[8][128];
    __shared__ float Bs[8][128];

    const int tid = threadIdx.x;
    const int bm = blockIdx.y * 128;
    const int bn = blockIdx.x * 128;
    const int tm = (tid / 16) * 8;
    const int tn = (tid % 16) * 8;

    const int a_m = tid >> 1;            // 0..127
    const int a_c = (tid & 1) * 4;       // 0 or 4
    const int b_k = tid >> 5;            // 0..7
    const int b_n = (tid & 31) * 4;      // 0..124

    float acc[8][8];
#pragma unroll
    for (int i = 0; i < 8; i++)
#pragma unroll
        for (int j = 0; j < 8; j++) acc[i][j] = 0.f;

    for (int k0 = 0; k0 < K; k0 += 8) {
        float4 av = *(const float4*)&A[(size_t)(bm + a_m) * K + k0 + a_c];
        As[a_c + 0][a_m] = av.x;
        As[a_c + 1][a_m] = av.y;
        As[a_c + 2][a_m] = av.z;
        As[a_c + 3][a_m] = av.w;
        *(float4*)&Bs[b_k][b_n] = *(const float4*)&B[(size_t)(k0 + b_k) * N + bn + b_n];
        __syncthreads();
#pragma unroll
        for (int k = 0; k < 8; k++) {
            float a[8], b[8];
#pragma unroll
            for (int i = 0; i < 4; i++) { ((float4*)a)[0] = *(float4*)&As[k][tm];
                                          ((float4*)a)[1] = *(float4*)&As[k][tm + 4]; break; }
#pragma unroll
            for (int j = 0; j < 4; j++) { ((float4*)b)[0] = *(float4*)&Bs[k][tn];
                                          ((float4*)b)[1] = *(float4*)&Bs[k][tn + 4]; break; }
#pragma unroll
            for (int i = 0; i < 8; i++)
#pragma unroll
                for (int j = 0; j < 8; j++) acc[i][j] += a[i] * b[j];
        }
        __syncthreads();
    }

#pragma unroll
    for (int i = 0; i < 8; i++) {
        const int row = bm + tm + i;
        const float bv = (mode != 0) ? bias[row] : 0.f;
        float* crow = C + (size_t)row * N + bn + tn;
        const float* rrow = (mode == 2) ? (R + (size_t)row * N + bn + tn) : nullptr;
#pragma unroll
        for (int j = 0; j < 8; j++) {
            float v = acc[i][j] + bv;
            if (mode == 1) v = fmaxf(v, 0.f);
            if (mode == 2) v += rrow[j];
            crow[j] = v;
        }
    }
}

// ---------------- scores: C[h] = KX[h]^T @ KX[h], K=Qc=64 ----------------
// C[h][i][j] = sum_q KX[h][q][i] * KX[h][q][j]
__global__ void __launch_bounds__(256) sgemm_tn_scores(
    const float* __restrict__ KX, float* __restrict__ S)
{
    const int h = blockIdx.z;
    const float* A = KX + (size_t)h * Qc * Nc;
    float* C = S + (size_t)h * Nc * Nc;

    __shared__ float As[8][128];
    __shared__ float Bs[8][128];

    const int tid = threadIdx.x;
    const int bm = blockIdx.y * 128;
    const int bn = blockIdx.x * 128;
    const int tm = (tid / 16) * 8;
    const int tn = (tid % 16) * 8;

    const int t_k = tid >> 5;
    const int t_x = (tid & 31) * 4;

    float acc[8][8];
#pragma unroll
    for (int i = 0; i < 8; i++)
#pragma unroll
        for (int j = 0; j < 8; j++) acc[i][j] = 0.f;

    for (int k0 = 0; k0 < Qc; k0 += 8) {
        *(float4*)&As[t_k][t_x] = *(const float4*)&A[(size_t)(k0 + t_k) * Nc + bm + t_x];
        *(float4*)&Bs[t_k][t_x] = *(const float4*)&A[(size_t)(k0 + t_k) * Nc + bn + t_x];
        __syncthreads();
#pragma unroll
        for (int k = 0; k < 8; k++) {
            float a[8], b[8];
            ((float4*)a)[0] = *(float4*)&As[k][tm];
            ((float4*)a)[1] = *(float4*)&As[k][tm + 4];
            ((float4*)b)[0] = *(float4*)&Bs[k][tn];
            ((float4*)b)[1] = *(float4*)&Bs[k][tn + 4];
#pragma unroll
            for (int i = 0; i < 8; i++)
#pragma unroll
                for (int j = 0; j < 8; j++) acc[i][j] += a[i] * b[j];
        }
        __syncthreads();
    }

#pragma unroll
    for (int i = 0; i < 8; i++) {
        float* crow = C + (size_t)(bm + tm + i) * Nc + bn + tn;
#pragma unroll
        for (int j = 0; j < 8; j++) crow[j] = acc[i][j];
    }
}

// ---------------- argmax mask + sparse scatter ----------------------------
// One block per (row n, head h). Finds max of scores[h][n][:], collects all
// m with score >= max-0.5, computes w = active/row_sum, then
// attn[:,m] += w * Y[h][:,n] for every hit m.
__global__ void __launch_bounds__(256) argmax_scatter(
    const float* __restrict__ S, const float* __restrict__ Y,
    float* __restrict__ attn)
{
    const int n = blockIdx.x;
    const int h = blockIdx.y;
    const int tid = threadIdx.x;
    const float* row = S + ((size_t)h * Nc + n) * Nc;

    __shared__ float red[256];
    __shared__ int list[Nc];
    __shared__ int s_cnt;
    __shared__ float wy[Dc];

    float mx = -1e30f;
    for (int m = tid; m < Nc; m += 256) mx = fmaxf(mx, row[m]);
    red[tid] = mx;
    __syncthreads();
#pragma unroll
    for (int s = 128; s > 0; s >>= 1) {
        if (tid < s) red[tid] = fmaxf(red[tid], red[tid + s]);
        __syncthreads();
    }
    const float rmax = red[0];
    const float thr = rmax - 0.5f;

    if (tid == 0) s_cnt = 0;
    __syncthreads();
    for (int m = tid; m < Nc; m += 256) {
        if (row[m] >= thr) {
            int p = atomicAdd(&s_cnt, 1);
            list[p] = m;
        }
    }
    __syncthreads();

    const int cnt = s_cnt;
    const float active = (fabsf(rmax) > 0.5f) ? 1.f : 0.f;
    const float w = active / (float)(cnt > 0 ? cnt : 1);
    if (w == 0.f) return;

    // preload w * Y[h][:,n] into smem (column of Y, strided reads once)
    const float* ycol = Y + (size_t)h * Dc * Nc + n;
    for (int d = tid; d < Dc; d += 256) wy[d] = w * ycol[(size_t)d * Nc];
    __syncthreads();

    for (int i = 0; i < cnt; i++) {
        const int m = list[i];
        float* acol = attn + m;
        for (int d = tid; d < Dc; d += 256)
            atomicAdd(&acol[(size_t)d * Nc], wy[d]);
    }
}

// --------------------------------------------------------------------------
extern "C" void kernel_launch(void* const* d_in, const int* in_sizes, int n_in,
                              void* d_out, int out_size)
{
    const float* X  = (const float*)d_in[0];
    const float* Kp = (const float*)d_in[1];
    const float* Vp = (const float*)d_in[2];
    const float* W1 = (const float*)d_in[3];
    const float* b1 = (const float*)d_in[4];
    const float* W2 = (const float*)d_in[5];
    const float* b2 = (const float*)d_in[6];

    float *gX, *gAttn, *gKX, *gScores, *gY, *gFF1;
    cudaGetSymbolAddress((void**)&gX,      g_X);
    cudaGetSymbolAddress((void**)&gAttn,   g_attn);
    cudaGetSymbolAddress((void**)&gKX,     g_KX);
    cudaGetSymbolAddress((void**)&gScores, g_scores);
    cudaGetSymbolAddress((void**)&gY,      g_Y);
    cudaGetSymbolAddress((void**)&gFF1,    g_ff1);

    cudaMemcpyAsync(gX, X, (size_t)Dc * Nc * sizeof(float),
                    cudaMemcpyDeviceToDevice);

    for (int l = 0; l < Lc; l++) {
        const float* Kl  = Kp + (size_t)l * Hc * Qc * Dc;
        const float* Vl  = Vp + (size_t)l * Hc * Dc * Dc;
        const float* W1l = W1 + (size_t)l * DFFc * Dc;
        const float* b1l = b1 + (size_t)l * DFFc;
        const float* W2l = W2 + (size_t)l * Dc * DFFc;
        const float* b2l = b2 + (size_t)l * Dc;

        // 1) KX = K_l @ X   [H*Q=256, N], K=512
        sgemm_nn<<<dim3(Nc / 128, (Hc * Qc) / 128, 1), 256>>>(
            Kl, gX, gKX, Hc * Qc, Nc, Dc, 0, 0, nullptr, nullptr, 0);

        // 2) scores[h] = KX[h]^T @ KX[h]
        sgemm_tn_scores<<<dim3(Nc / 128, Nc / 128, Hc), 256>>>(gKX, gScores);

        // 3) Y[h] = V_lh @ X   (batched over heads)
        sgemm_nn<<<dim3(Nc / 128, Dc / 128, Hc), 256>>>(
            Vl, gX, gY, Dc, Nc, Dc,
            (long long)Dc * Dc, (long long)Dc * Nc, nullptr, nullptr, 0);

        // 4) attn = X
        cudaMemcpyAsync(gAttn, gX, (size_t)Dc * Nc * sizeof(float),
                        cudaMemcpyDeviceToDevice);

        // 5) attn += sum_h Y[h] @ weights[h]  (sparse argmax scatter)
        argmax_scatter<<<dim3(Nc, Hc), 256>>>(gScores, gY, gAttn);

        // 6) ff1 = relu(W1_l @ attn + b1_l)
        sgemm_nn<<<dim3(Nc / 128, DFFc / 128, 1), 256>>>(
            W1l, gAttn, gFF1, DFFc, Nc, Dc, 0, 0, b1l, nullptr, 1);

        // 7) X = attn + W2_l @ ff1 + b2_l
        sgemm_nn<<<dim3(Nc / 128, Dc / 128, 1), 256>>>(
            W2l, gFF1, gX, Dc, Nc, DFFc, 0, 0, b2l, gAttn, 2);
    }

    cudaMemcpyAsync(d_out, gX, (size_t)Dc * Nc * sizeof(float),
                    cudaMemcpyDeviceToDevice);
}

// round 2
// speedup vs baseline: 1.4281x; 1.4281x over previous
#include <cuda_runtime.h>
#include <cstdint>

#define Lc   8
#define Hc   4
#define Qc   64
#define Dc   512
#define Nc   2048
#define DFFc 2048

// ---------------- device scratch (no allocations allowed) ----------------
__device__ float g_X[Dc * Nc];                         // current activations [D,N]
__device__ float g_attn[Dc * Nc];                      // attn = X + scatter  [D,N]
__device__ float g_KX[Hc * Qc * Nc];                   // [H,Q,N]
__device__ float g_scores[(size_t)Hc * Nc * Nc];       // [H,N,N]  (64 MB)
__device__ float g_Y[Hc * Dc * Nc];                    // V_h @ X  [H,D,N]
__device__ float g_ff1[DFFc * Nc];                     // [DFF,N]

// ---------------- double-buffered NN SGEMM ----------------
// C = A@B (+bias)(+relu)(+residual). A:[M,K], B:[K,N], C:[M,N] row-major.
// BMxBNx16 tiles, TMxTN per-thread microtile, one __syncthreads per k-tile.
// mode 0: C = AB; 1: C = relu(AB + bias[row]); 2: C = AB + bias[row] + R
template<int BM, int BN, int THREADS, int TM, int TN, int MINB>
__global__ void __launch_bounds__(THREADS, MINB) sgemm_db(
    const float* __restrict__ A, const float* __restrict__ B,
    float* __restrict__ C, int M, int N, int K,
    long long strideA, long long strideC,
    const float* __restrict__ bias, const float* __restrict__ R, int mode)
{
    constexpr int BK = 16;
    constexpr int TX = BN / TN;
    constexpr int TY = BM / TM;
    static_assert(TX * TY == THREADS, "thread grid mismatch");

    constexpr int AF4  = BK / 4;            // float4 per A row
    constexpr int ARPP = THREADS / AF4;     // A rows per pass
    constexpr int APASS = BM / ARPP;
    constexpr int BF4  = BN / 4;
    constexpr int BRPP = THREADS / BF4;
    constexpr int BPASS = BK / BRPP;

    __shared__ float As[2][BK][BM];
    __shared__ float Bs[2][BK][BN];

    const int bz = blockIdx.z;
    A += (size_t)bz * strideA;
    C += (size_t)bz * strideC;

    const int tid = threadIdx.x;
    const int bm = blockIdx.y * BM;
    const int bn = blockIdx.x * BN;
    const int tx = tid % TX;
    const int ty = tid / TX;
    const int row0 = ty * TM;
    const int col0 = tx * TN;

    const int a_row = tid / AF4;
    const int a_col = (tid % AF4) * 4;
    const int b_row = tid / BF4;
    const int b_col = (tid % BF4) * 4;

    float4 a_st[APASS], b_st[BPASS];

#define GLOAD(k0)                                                              \
    {                                                                          \
        _Pragma("unroll")                                                      \
        for (int p = 0; p < APASS; p++)                                        \
            a_st[p] = *(const float4*)&A[(size_t)(bm + a_row + p * ARPP) * K   \
                                         + (k0) + a_col];                      \
        _Pragma("unroll")                                                      \
        for (int p = 0; p < BPASS; p++)                                        \
            b_st[p] = *(const float4*)&B[(size_t)((k0) + b_row + p * BRPP) * N \
                                         + bn + b_col];                        \
    }

#define SSTORE(buf)                                                            \
    {                                                                          \
        _Pragma("unroll")                                                      \
        for (int p = 0; p < APASS; p++) {                                      \
            As[buf][a_col + 0][a_row + p * ARPP] = a_st[p].x;                  \
            As[buf][a_col + 1][a_row + p * ARPP] = a_st[p].y;                  \
            As[buf][a_col + 2][a_row + p * ARPP] = a_st[p].z;                  \
            As[buf][a_col + 3][a_row + p * ARPP] = a_st[p].w;                  \
        }                                                                      \
        _Pragma("unroll")                                                      \
        for (int p = 0; p < BPASS; p++)                                        \
            *(float4*)&Bs[buf][b_row + p * BRPP][b_col] = b_st[p];             \
    }

    float acc[TM][TN];
#pragma unroll
    for (int i = 0; i < TM; i++)
#pragma unroll
        for (int j = 0; j < TN; j++) acc[i][j] = 0.f;

    GLOAD(0);
    SSTORE(0);
    __syncthreads();

    const int KT = K / BK;
    for (int kt = 0; kt < KT; kt++) {
        const int cur = kt & 1;
        if (kt + 1 < KT) GLOAD((kt + 1) * BK);
#pragma unroll
        for (int k = 0; k < BK; k++) {
            float a[TM], b[TN];
#pragma unroll
            for (int i = 0; i < TM; i += 4)
                *(float4*)&a[i] = *(const float4*)&As[cur][k][row0 + i];
#pragma unroll
            for (int j = 0; j < TN; j += 4)
                *(float4*)&b[j] = *(const float4*)&Bs[cur][k][col0 + j];
#pragma unroll
            for (int i = 0; i < TM; i++)
#pragma unroll
                for (int j = 0; j < TN; j++)
                    acc[i][j] = fmaf(a[i], b[j], acc[i][j]);
        }
        if (kt + 1 < KT) {
            SSTORE(cur ^ 1);
            __syncthreads();
        }
    }

#pragma unroll
    for (int i = 0; i < TM; i++) {
        const int row = bm + row0 + i;
        const float bv = (mode != 0) ? bias[row] : 0.f;
        float* crow = C + (size_t)row * N + bn + col0;
        const float* rrow = (mode == 2) ? (R + (size_t)row * N + bn + col0) : nullptr;
#pragma unroll
        for (int j = 0; j < TN; j++) {
            float v = acc[i][j] + bv;
            if (mode == 1) v = fmaxf(v, 0.f);
            if (mode == 2) v += rrow[j];
            crow[j] = v;
        }
    }
#undef GLOAD
#undef SSTORE
}

// ---------------- scores: S[h] = KX[h]^T @ KX[h], double-buffered ---------
// S[h][i][j] = sum_q KX[h][q][bm+i] * KX[h][q][bn+j].  K = Qc = 64.
__global__ void __launch_bounds__(256, 2) scores_db(
    const float* __restrict__ KX, float* __restrict__ S)
{
    constexpr int BK = 16;
    const int h = blockIdx.z;
    const float* A = KX + (size_t)h * Qc * Nc;
    float* C = S + (size_t)h * Nc * Nc;

    __shared__ float As[2][BK][128];
    __shared__ float Bs[2][BK][128];

    const int tid = threadIdx.x;
    const int bm = blockIdx.y * 128;
    const int bn = blockIdx.x * 128;
    const int tx = tid % 16;
    const int ty = tid / 16;
    const int row0 = ty * 8;
    const int col0 = tx * 8;

    // both operands: rows of KX (B-style), 16x128 tile, 8 rows/pass, 2 passes
    const int l_row = tid / 32;
    const int l_col = (tid % 32) * 4;

    float4 a_st[2], b_st[2];

#define SGLOAD(k0)                                                             \
    {                                                                          \
        _Pragma("unroll")                                                      \
        for (int p = 0; p < 2; p++) {                                          \
            a_st[p] = *(const float4*)&A[(size_t)((k0) + l_row + p * 8) * Nc + bm + l_col]; \
            b_st[p] = *(const float4*)&A[(size_t)((k0) + l_row + p * 8) * Nc + bn + l_col]; \
        }                                                                      \
    }
#define SSSTORE(buf)                                                           \
    {                                                                          \
        _Pragma("unroll")                                                      \
        for (int p = 0; p < 2; p++) {                                          \
            *(float4*)&As[buf][l_row + p * 8][l_col] = a_st[p];                \
            *(float4*)&Bs[buf][l_row + p * 8][l_col] = b_st[p];                \
        }                                                                      \
    }

    float acc[8][8];
#pragma unroll
    for (int i = 0; i < 8; i++)
#pragma unroll
        for (int j = 0; j < 8; j++) acc[i][j] = 0.f;

    SGLOAD(0);
    SSSTORE(0);
    __syncthreads();

    const int KT = Qc / BK;  // 4
#pragma unroll
    for (int kt = 0; kt < KT; kt++) {
        const int cur = kt & 1;
        if (kt + 1 < KT) SGLOAD((kt + 1) * BK);
#pragma unroll
        for (int k = 0; k < BK; k++) {
            float a[8], b[8];
            *(float4*)&a[0] = *(const float4*)&As[cur][k][row0];
            *(float4*)&a[4] = *(const float4*)&As[cur][k][row0 + 4];
            *(float4*)&b[0] = *(const float4*)&Bs[cur][k][col0];
            *(float4*)&b[4] = *(const float4*)&Bs[cur][k][col0 + 4];
#pragma unroll
            for (int i = 0; i < 8; i++)
#pragma unroll
                for (int j = 0; j < 8; j++)
                    acc[i][j] = fmaf(a[i], b[j], acc[i][j]);
        }
        if (kt + 1 < KT) {
            SSSTORE(cur ^ 1);
            __syncthreads();
        }
    }

#pragma unroll
    for (int i = 0; i < 8; i++) {
        float* crow = C + (size_t)(bm + row0 + i) * Nc + bn + col0;
        *(float4*)&crow[0] = *(float4*)&acc[i][0];
        *(float4*)&crow[4] = *(float4*)&acc[i][4];
    }
#undef SGLOAD
#undef SSSTORE
}

// ---------------- argmax mask + sparse scatter ----------------------------
__global__ void __launch_bounds__(256) argmax_scatter(
    const float* __restrict__ S, const float* __restrict__ Y,
    float* __restrict__ attn)
{
    const int n = blockIdx.x;
    const int h = blockIdx.y;
    const int tid = threadIdx.x;
    const float* row = S + ((size_t)h * Nc + n) * Nc;

    __shared__ float red[256];
    __shared__ int list[Nc];
    __shared__ int s_cnt;
    __shared__ float wy[Dc];

    float mx = -1e30f;
    for (int m = tid; m < Nc; m += 256) mx = fmaxf(mx, row[m]);
    red[tid] = mx;
    __syncthreads();
#pragma unroll
    for (int s = 128; s > 0; s >>= 1) {
        if (tid < s) red[tid] = fmaxf(red[tid], red[tid + s]);
        __syncthreads();
    }
    const float rmax = red[0];
    const float thr = rmax - 0.5f;

    if (tid == 0) s_cnt = 0;
    __syncthreads();
    for (int m = tid; m < Nc; m += 256) {
        if (row[m] >= thr) {
            int p = atomicAdd(&s_cnt, 1);
            list[p] = m;
        }
    }
    __syncthreads();

    const int cnt = s_cnt;
    const float active = (fabsf(rmax) > 0.5f) ? 1.f : 0.f;
    const float w = active / (float)(cnt > 0 ? cnt : 1);
    if (w == 0.f) return;

    const float* ycol = Y + (size_t)h * Dc * Nc + n;
    for (int d = tid; d < Dc; d += 256) wy[d] = w * ycol[(size_t)d * Nc];
    __syncthreads();

    for (int i = 0; i < cnt; i++) {
        const int m = list[i];
        float* acol = attn + m;
        for (int d = tid; d < Dc; d += 256)
            atomicAdd(&acol[(size_t)d * Nc], wy[d]);
    }
}

// --------------------------------------------------------------------------
extern "C" void kernel_launch(void* const* d_in, const int* in_sizes, int n_in,
                              void* d_out, int out_size)
{
    const float* X  = (const float*)d_in[0];
    const float* Kp = (const float*)d_in[1];
    const float* Vp = (const float*)d_in[2];
    const float* W1 = (const float*)d_in[3];
    const float* b1 = (const float*)d_in[4];
    const float* W2 = (const float*)d_in[5];
    const float* b2 = (const float*)d_in[6];

    float *gX, *gAttn, *gKX, *gScores, *gY, *gFF1;
    cudaGetSymbolAddress((void**)&gX,      g_X);
    cudaGetSymbolAddress((void**)&gAttn,   g_attn);
    cudaGetSymbolAddress((void**)&gKX,     g_KX);
    cudaGetSymbolAddress((void**)&gScores, g_scores);
    cudaGetSymbolAddress((void**)&gY,      g_Y);
    cudaGetSymbolAddress((void**)&gFF1,    g_ff1);

    cudaMemcpyAsync(gX, X, (size_t)Dc * Nc * sizeof(float),
                    cudaMemcpyDeviceToDevice);

    for (int l = 0; l < Lc; l++) {
        const float* Kl  = Kp + (size_t)l * Hc * Qc * Dc;
        const float* Vl  = Vp + (size_t)l * Hc * Dc * Dc;
        const float* W1l = W1 + (size_t)l * DFFc * Dc;
        const float* b1l = b1 + (size_t)l * DFFc;
        const float* W2l = W2 + (size_t)l * Dc * DFFc;
        const float* b2l = b2 + (size_t)l * Dc;

        // 1) KX = K_l @ X   [256, 2048], K=512 — 64x64 tiles -> 128 blocks
        sgemm_db<64, 64, 128, 8, 4, 4><<<dim3(Nc / 64, (Hc * Qc) / 64, 1), 128>>>(
            Kl, gX, gKX, Hc * Qc, Nc, Dc, 0, 0, nullptr, nullptr, 0);

        // 2) scores[h] = KX[h]^T @ KX[h]  — 1024 blocks
        scores_db<<<dim3(Nc / 128, Nc / 128, Hc), 256>>>(gKX, gScores);

        // 3) Y[h] = V_lh @ X  (batched over heads) — 256 blocks
        sgemm_db<128, 128, 256, 8, 8, 2><<<dim3(Nc / 128, Dc / 128, Hc), 256>>>(
            Vl, gX, gY, Dc, Nc, Dc,
            (long long)Dc * Dc, (long long)Dc * Nc, nullptr, nullptr, 0);

        // 4) attn = X
        cudaMemcpyAsync(gAttn, gX, (size_t)Dc * Nc * sizeof(float),
                        cudaMemcpyDeviceToDevice);

        // 5) attn += sum_h Y[h] @ weights[h]  (sparse argmax scatter)
        argmax_scatter<<<dim3(Nc, Hc), 256>>>(gScores, gY, gAttn);

        // 6) ff1 = relu(W1_l @ attn + b1_l) — 256 blocks
        sgemm_db<128, 128, 256, 8, 8, 2><<<dim3(Nc / 128, DFFc / 128, 1), 256>>>(
            W1l, gAttn, gFF1, DFFc, Nc, Dc, 0, 0, b1l, nullptr, 1);

        // 7) X = attn + W2_l @ ff1 + b2_l — 64x128 tiles -> 128 blocks
        sgemm_db<64, 128, 128, 8, 8, 4><<<dim3(Nc / 128, Dc / 64, 1), 128>>>(
            W2l, gFF1, gX, Dc, Nc, DFFc, 0, 0, b2l, gAttn, 2);
    }

    cudaMemcpyAsync(d_out, gX, (size_t)Dc * Nc * sizeof(float),
                    cudaMemcpyDeviceToDevice);
}

// round 4
// speedup vs baseline: 2.2876x; 1.6019x over previous
#include <cuda_runtime.h>
#include <cuda_bf16.h>
#include <mma.h>
#include <cstdint>

using namespace nvcuda;

#define Lc   8
#define Hc   4
#define Qc   64
#define Dc   512
#define Nc   2048
#define DFFc 2048

// ---------------- device scratch (no allocations allowed) ----------------
__device__ float g_X[Dc * Nc];
__device__ float g_attn[Dc * Nc];
__device__ float g_KX[Hc * Qc * Nc];
__device__ float g_scores[(size_t)Hc * Nc * Nc];
__device__ float g_Y[Hc * Dc * Nc];
__device__ float g_ff1[DFFc * Nc];

// Split a float4 into bf16 high/low parts and store 4+4 bf16 (8B each dst).
__device__ __forceinline__ void split_store4(__nv_bfloat16* __restrict__ Hd,
                                             __nv_bfloat16* __restrict__ Ld,
                                             float4 v)
{
    __nv_bfloat162 h0 = __floats2bfloat162_rn(v.x, v.y);
    __nv_bfloat162 h1 = __floats2bfloat162_rn(v.z, v.w);
    float2 f0 = __bfloat1622float2(h0);
    float2 f1 = __bfloat1622float2(h1);
    __nv_bfloat162 l0 = __floats2bfloat162_rn(v.x - f0.x, v.y - f0.y);
    __nv_bfloat162 l1 = __floats2bfloat162_rn(v.z - f1.x, v.w - f1.y);
    *(__nv_bfloat162*)(Hd)     = h0;
    *(__nv_bfloat162*)(Hd + 2) = h1;
    *(__nv_bfloat162*)(Ld)     = l0;
    *(__nv_bfloat162*)(Ld + 2) = l1;
}

// ============ WMMA bf16 3x GEMM: C = A@B (+bias)(+relu)(+residual) ========
// A:[M,K] row-major, B:[K,N] row-major, C:[M,N] row-major.
// Block tile BM x BN x 32 (fp32 k), double-buffered smem, warp tile 32x64.
// mode 0: C=AB (direct wmma store); 1: C=relu(AB+bias); 2: C=AB+bias+R
template<int BM, int BN, int WARPS_M, int WARPS_N>
__global__ void __launch_bounds__(WARPS_M * WARPS_N * 32) wmma_gemm(
    const float* __restrict__ A, const float* __restrict__ B,
    float* __restrict__ C, int M, int N, int K,
    long long strideA, long long strideC,
    const float* __restrict__ bias, const float* __restrict__ R, int mode)
{
    constexpr int THREADS = WARPS_M * WARPS_N * 32;
    constexpr int BK = 32;
    constexpr int AP = 48;               // A pitch (elements)
    constexpr int BP = 144;              // B pitch (elements)
    constexpr int A_ELE = BM * AP;
    constexpr int B_ELE = BK * BP;
    constexpr int BUFE  = 2 * A_ELE + 2 * B_ELE;  // Ah,Al,Bh,Bl (elements)
    constexpr int MF = 2, NF = 4;        // 32x64 warp tile
    constexpr int AF4T = BM * (BK / 4) / THREADS;
    constexpr int BF4T = BK * (BN / 4) / THREADS;

    extern __shared__ char smc[];
    __nv_bfloat16* smb = (__nv_bfloat16*)smc;

    A += (size_t)blockIdx.z * strideA;
    C += (size_t)blockIdx.z * strideC;
    const int tid = threadIdx.x;
    const int w   = tid >> 5;
    const int bm  = blockIdx.y * BM;
    const int bn  = blockIdx.x * BN;
    const int wm0 = (w % WARPS_M) * 32;
    const int wn0 = (w / WARPS_M) * 64;

    const int ar  = (tid * 1) / (BK / 4) ;   // will recompute per-pass below
    (void)ar;

    float4 a_reg[AF4T], b_reg[BF4T];

#define GLOAD(k0)                                                              \
    {                                                                          \
        _Pragma("unroll")                                                      \
        for (int p = 0; p < AF4T; p++) {                                       \
            const int id = tid + p * THREADS;                                  \
            const int r = id >> 3, c4 = id & 7;                                \
            a_reg[p] = *(const float4*)&A[(size_t)(bm + r) * K + (k0) + c4*4]; \
        }                                                                      \
        _Pragma("unroll")                                                      \
        for (int p = 0; p < BF4T; p++) {                                       \
            const int id = tid + p * THREADS;                                  \
            const int r = id / (BN / 4), c4 = id % (BN / 4);                   \
            b_reg[p] = *(const float4*)&B[(size_t)((k0) + r) * N + bn + c4*4]; \
        }                                                                      \
    }

#define SSTORE(buf)                                                            \
    {                                                                          \
        __nv_bfloat16* aH = smb + (buf) * BUFE;                                \
        __nv_bfloat16* aL = aH + A_ELE;                                        \
        __nv_bfloat16* bH = aH + 2 * A_ELE;                                    \
        __nv_bfloat16* bL = bH + B_ELE;                                        \
        _Pragma("unroll")                                                      \
        for (int p = 0; p < AF4T; p++) {                                       \
            const int id = tid + p * THREADS;                                  \
            const int r = id >> 3, c4 = id & 7;                                \
            split_store4(aH + r * AP + c4 * 4, aL + r * AP + c4 * 4, a_reg[p]);\
        }                                                                      \
        _Pragma("unroll")                                                      \
        for (int p = 0; p < BF4T; p++) {                                       \
            const int id = tid + p * THREADS;                                  \
            const int r = id / (BN / 4), c4 = id % (BN / 4);                   \
            split_store4(bH + r * BP + c4 * 4, bL + r * BP + c4 * 4, b_reg[p]);\
        }                                                                      \
    }

    wmma::fragment<wmma::accumulator, 16, 16, 16, float> acc[MF][NF];
#pragma unroll
    for (int i = 0; i < MF; i++)
#pragma unroll
        for (int j = 0; j < NF; j++) wmma::fill_fragment(acc[i][j], 0.f);

    GLOAD(0);
    SSTORE(0);
    __syncthreads();

    const int KT = K / BK;
    for (int kt = 0; kt < KT; kt++) {
        const int cur = kt & 1;
        if (kt + 1 < KT) GLOAD((kt + 1) * BK);

        const __nv_bfloat16* aH = smb + cur * BUFE;
        const __nv_bfloat16* aL = aH + A_ELE;
        const __nv_bfloat16* bH = aH + 2 * A_ELE;
        const __nv_bfloat16* bL = bH + B_ELE;

#pragma unroll
        for (int kks = 0; kks < 2; kks++) {
            const int kk = kks * 16;
            wmma::fragment<wmma::matrix_a, 16, 16, 16, __nv_bfloat16, wmma::row_major> fAh[MF], fAl[MF];
            wmma::fragment<wmma::matrix_b, 16, 16, 16, __nv_bfloat16, wmma::row_major> fBh[NF], fBl[NF];
#pragma unroll
            for (int i = 0; i < MF; i++) {
                wmma::load_matrix_sync(fAh[i], aH + (wm0 + i * 16) * AP + kk, AP);
                wmma::load_matrix_sync(fAl[i], aL + (wm0 + i * 16) * AP + kk, AP);
            }
#pragma unroll
            for (int j = 0; j < NF; j++) {
                wmma::load_matrix_sync(fBh[j], bH + kk * BP + wn0 + j * 16, BP);
                wmma::load_matrix_sync(fBl[j], bL + kk * BP + wn0 + j * 16, BP);
            }
#pragma unroll
            for (int i = 0; i < MF; i++)
#pragma unroll
                for (int j = 0; j < NF; j++) {
                    wmma::mma_sync(acc[i][j], fAh[i], fBh[j], acc[i][j]);
                    wmma::mma_sync(acc[i][j], fAh[i], fBl[j], acc[i][j]);
                    wmma::mma_sync(acc[i][j], fAl[i], fBh[j], acc[i][j]);
                }
        }

        if (kt + 1 < KT) {
            SSTORE(cur ^ 1);
            __syncthreads();
        }
    }

    if (mode == 0) {
        // direct store to global
#pragma unroll
        for (int i = 0; i < MF; i++)
#pragma unroll
            for (int j = 0; j < NF; j++)
                wmma::store_matrix_sync(
                    &C[(size_t)(bm + wm0 + i * 16) * N + bn + wn0 + j * 16],
                    acc[i][j], N, wmma::mem_row_major);
    } else {
        // stage to smem, then fused bias/relu/residual epilogue
        __syncthreads();
        float* cs = (float*)smc;
#pragma unroll
        for (int i = 0; i < MF; i++)
#pragma unroll
            for (int j = 0; j < NF; j++)
                wmma::store_matrix_sync(
                    cs + (size_t)(wm0 + i * 16) * BN + wn0 + j * 16,
                    acc[i][j], BN, wmma::mem_row_major);
        __syncthreads();

        constexpr int CF4T = BM * BN / 4 / THREADS;
#pragma unroll
        for (int p = 0; p < CF4T; p++) {
            const int id = tid + p * THREADS;
            const int row = id / (BN / 4), c4 = id % (BN / 4);
            float4 v = ((const float4*)cs)[id];
            const int grow = bm + row;
            const float bv = bias[grow];
            v.x += bv; v.y += bv; v.z += bv; v.w += bv;
            if (mode == 1) {
                v.x = fmaxf(v.x, 0.f); v.y = fmaxf(v.y, 0.f);
                v.z = fmaxf(v.z, 0.f); v.w = fmaxf(v.w, 0.f);
            } else {
                float4 r4 = *(const float4*)&R[(size_t)grow * N + bn + c4 * 4];
                v.x += r4.x; v.y += r4.y; v.z += r4.z; v.w += r4.w;
            }
            *(float4*)&C[(size_t)grow * N + bn + c4 * 4] = v;
        }
    }
#undef GLOAD
#undef SSTORE
}

// ============ scores: S[h] = KX[h]^T @ KX[h] via WMMA bf16 3x ==============
// KX[h]: [Q=64, N] row-major. Block computes S[h][bm:bm+128][bn:bn+128].
// A fragment = col_major view of the K-major tile (free transpose).
__global__ void __launch_bounds__(256) wmma_scores(
    const float* __restrict__ KX, float* __restrict__ S)
{
    constexpr int P = 144;
    constexpr int T_ELE = Qc * P;        // one operand's h or l plane

    extern __shared__ char smc[];
    __nv_bfloat16* aH = (__nv_bfloat16*)smc;
    __nv_bfloat16* aL = aH + T_ELE;
    __nv_bfloat16* bH = aL + T_ELE;
    __nv_bfloat16* bL = bH + T_ELE;

    const int h = blockIdx.z;
    const float* A = KX + (size_t)h * Qc * Nc;
    float* C = S + (size_t)h * Nc * Nc;

    const int tid = threadIdx.x;
    const int w = tid >> 5;
    const int bm = blockIdx.y * 128;
    const int bn = blockIdx.x * 128;
    const int wm0 = (w % 4) * 32;
    const int wn0 = (w / 4) * 64;

#pragma unroll
    for (int p = 0; p < 8; p++) {
        const int id = tid + p * 256;
        const int r = id >> 5, c4 = id & 31;
        float4 va = *(const float4*)&A[(size_t)r * Nc + bm + c4 * 4];
        float4 vb = *(const float4*)&A[(size_t)r * Nc + bn + c4 * 4];
        split_store4(aH + r * P + c4 * 4, aL + r * P + c4 * 4, va);
        split_store4(bH + r * P + c4 * 4, bL + r * P + c4 * 4, vb);
    }
    __syncthreads();

    wmma::fragment<wmma::accumulator, 16, 16, 16, float> acc[2][4];
#pragma unroll
    for (int i = 0; i < 2; i++)
#pragma unroll
        for (int j = 0; j < 4; j++) wmma::fill_fragment(acc[i][j], 0.f);

#pragma unroll
    for (int kks = 0; kks < 4; kks++) {
        const int kk = kks * 16;
        wmma::fragment<wmma::matrix_a, 16, 16, 16, __nv_bfloat16, wmma::col_major> fAh[2], fAl[2];
        wmma::fragment<wmma::matrix_b, 16, 16, 16, __nv_bfloat16, wmma::row_major> fBh[4], fBl[4];
#pragma unroll
        for (int i = 0; i < 2; i++) {
            wmma::load_matrix_sync(fAh[i], aH + kk * P + wm0 + i * 16, P);
            wmma::load_matrix_sync(fAl[i], aL + kk * P + wm0 + i * 16, P);
        }
#pragma unroll
        for (int j = 0; j < 4; j++) {
            wmma::load_matrix_sync(fBh[j], bH + kk * P + wn0 + j * 16, P);
            wmma::load_matrix_sync(fBl[j], bL + kk * P + wn0 + j * 16, P);
        }
#pragma unroll
        for (int i = 0; i < 2; i++)
#pragma unroll
            for (int j = 0; j < 4; j++) {
                wmma::mma_sync(acc[i][j], fAh[i], fBh[j], acc[i][j]);
                wmma::mma_sync(acc[i][j], fAh[i], fBl[j], acc[i][j]);
                wmma::mma_sync(acc[i][j], fAl[i], fBh[j], acc[i][j]);
            }
    }

#pragma unroll
    for (int i = 0; i < 2; i++)
#pragma unroll
        for (int j = 0; j < 4; j++)
            wmma::store_matrix_sync(
                &C[(size_t)(bm + wm0 + i * 16) * Nc + bn + wn0 + j * 16],
                acc[i][j], Nc, wmma::mem_row_major);
}

// ---------------- argmax mask + sparse scatter ----------------------------
__global__ void __launch_bounds__(256) argmax_scatter(
    const float* __restrict__ S, const float* __restrict__ Y,
    float* __restrict__ attn)
{
    const int n = blockIdx.x;
    const int h = blockIdx.y;
    const int tid = threadIdx.x;
    const float* row = S + ((size_t)h * Nc + n) * Nc;

    __shared__ float red[256];
    __shared__ int list[Nc];
    __shared__ int s_cnt;
    __shared__ float wy[Dc];

    float mx = -1e30f;
    for (int m = tid; m < Nc; m += 256) mx = fmaxf(mx, row[m]);
    red[tid] = mx;
    __syncthreads();
#pragma unroll
    for (int s = 128; s > 0; s >>= 1) {
        if (tid < s) red[tid] = fmaxf(red[tid], red[tid + s]);
        __syncthreads();
    }
    const float rmax = red[0];
    const float thr = rmax - 0.5f;

    if (tid == 0) s_cnt = 0;
    __syncthreads();
    for (int m = tid; m < Nc; m += 256) {
        if (row[m] >= thr) {
            int p = atomicAdd(&s_cnt, 1);
            list[p] = m;
        }
    }
    __syncthreads();

    const int cnt = s_cnt;
    const float active = (fabsf(rmax) > 0.5f) ? 1.f : 0.f;
    const float w = active / (float)(cnt > 0 ? cnt : 1);
    if (w == 0.f) return;

    const float* ycol = Y + (size_t)h * Dc * Nc + n;
    for (int d = tid; d < Dc; d += 256) wy[d] = w * ycol[(size_t)d * Nc];
    __syncthreads();

    for (int i = 0; i < cnt; i++) {
        const int m = list[i];
        float* acol = attn + m;
        for (int d = tid; d < Dc; d += 256)
            atomicAdd(&acol[(size_t)d * Nc], wy[d]);
    }
}

// --------------------------------------------------------------------------
extern "C" void kernel_launch(void* const* d_in, const int* in_sizes, int n_in,
                              void* d_out, int out_size)
{
    const float* X  = (const float*)d_in[0];
    const float* Kp = (const float*)d_in[1];
    const float* Vp = (const float*)d_in[2];
    const float* W1 = (const float*)d_in[3];
    const float* b1 = (const float*)d_in[4];
    const float* W2 = (const float*)d_in[5];
    const float* b2 = (const float*)d_in[6];

    float *gX, *gAttn, *gKX, *gScores, *gY, *gFF1;
    cudaGetSymbolAddress((void**)&gX,      g_X);
    cudaGetSymbolAddress((void**)&gAttn,   g_attn);
    cudaGetSymbolAddress((void**)&gKX,     g_KX);
    cudaGetSymbolAddress((void**)&gScores, g_scores);
    cudaGetSymbolAddress((void**)&gY,      g_Y);
    cudaGetSymbolAddress((void**)&gFF1,    g_ff1);

    // dynamic smem: buffers are (2*BM*48 + 2*32*144) bf16 elements, x2 buffers
    const int SM128 = 2 * (2 * 128 * 48 * 2 + 2 * 32 * 144 * 2);  // 86016
    const int SM64  = 2 * (2 *  64 * 48 * 2 + 2 * 32 * 144 * 2);  // 61440
    const int SMSC  = 4 * (Qc * 144 * 2);                          // 73728
    cudaFuncSetAttribute(wmma_gemm<128, 128, 4, 2>,
                         cudaFuncAttributeMaxDynamicSharedMemorySize, SM128);
    cudaFuncSetAttribute(wmma_gemm<64, 128, 2, 2>,
                         cudaFuncAttributeMaxDynamicSharedMemorySize, SM64);
    cudaFuncSetAttribute(wmma_scores,
                         cudaFuncAttributeMaxDynamicSharedMemorySize, SMSC);

    cudaMemcpyAsync(gX, X, (size_t)Dc * Nc * sizeof(float),
                    cudaMemcpyDeviceToDevice);

    for (int l = 0; l < Lc; l++) {
        const float* Kl  = Kp + (size_t)l * Hc * Qc * Dc;
        const float* Vl  = Vp + (size_t)l * Hc * Dc * Dc;
        const float* W1l = W1 + (size_t)l * DFFc * Dc;
        const float* b1l = b1 + (size_t)l * DFFc;
        const float* W2l = W2 + (size_t)l * Dc * DFFc;
        const float* b2l = b2 + (size_t)l * Dc;

        // 1) KX = K_l @ X   [256,2048], K=512
        wmma_gemm<64, 128, 2, 2><<<dim3(Nc / 128, (Hc * Qc) / 64, 1), 128, SM64>>>(
            Kl, gX, gKX, Hc * Qc, Nc, Dc, 0, 0, nullptr, nullptr, 0);

        // 2) scores[h] = KX[h]^T @ KX[h]
        wmma_scores<<<dim3(Nc / 128, Nc / 128, Hc), 256, SMSC>>>(gKX, gScores);

        // 3) Y[h] = V_lh @ X  (batched over heads)
        wmma_gemm<128, 128, 4, 2><<<dim3(Nc / 128, Dc / 128, Hc), 256, SM128>>>(
            Vl, gX, gY, Dc, Nc, Dc,
            (long long)Dc * Dc, (long long)Dc * Nc, nullptr, nullptr, 0);

        // 4) attn = X
        cudaMemcpyAsync(gAttn, gX, (size_t)Dc * Nc * sizeof(float),
                        cudaMemcpyDeviceToDevice);

        // 5) attn += sum_h Y[h] @ weights[h]  (sparse argmax scatter)
        argmax_scatter<<<dim3(Nc, Hc), 256>>>(gScores, gY, gAttn);

        // 6) ff1 = relu(W1_l @ attn + b1_l)
        wmma_gemm<128, 128, 4, 2><<<dim3(Nc / 128, DFFc / 128, 1), 256, SM128>>>(
            W1l, gAttn, gFF1, DFFc, Nc, Dc, 0, 0, b1l, nullptr, 1);

        // 7) X = attn + W2_l @ ff1 + b2_l
        wmma_gemm<64, 128, 2, 2><<<dim3(Nc / 128, Dc / 64, 1), 128, SM64>>>(
            W2l, gFF1, gX, Dc, Nc, DFFc, 0, 0, b2l, gAttn, 2);
    }

    cudaMemcpyAsync(d_out, gX, (size_t)Dc * Nc * sizeof(float),
                    cudaMemcpyDeviceToDevice);
}